// round 4
// baseline (speedup 1.0000x reference)
#include <cuda_runtime.h>
#include <math_constants.h>

#define NGROUPS 4096
#define NPAIRS  2048
#define DIM     64
#define MM      128
#define PSTR    68    // padded stride for 64-wide tiles
#define SSTR    132   // padded stride for 128-wide tiles
#define NTHREADS 1024

#define SMEM_BYTES  209408

__device__ int g_off[NGROUPS];
__device__ int g_size[NGROUPS];

// sizes may be int32 or int64 (LE); sizes are in [1,127] so int64 odd words are 0.
__global__ void scan_kernel(const int* __restrict__ raw) {
    __shared__ int wsum[32];
    const int stride =
        (raw[1] == 0 && raw[3] == 0 && raw[5] == 0 && raw[7] == 0) ? 2 : 1;
    int tid = threadIdx.x;              // 1024 threads, 4 items each
    int base = tid * 4;
    int v[4]; int s = 0;
#pragma unroll
    for (int i = 0; i < 4; i++) { v[i] = s; s += raw[(base + i) * stride]; }
    int lane = tid & 31, w = tid >> 5;
    int x = s;
#pragma unroll
    for (int d = 1; d < 32; d <<= 1) { int y = __shfl_up_sync(0xffffffffu, x, d); if (lane >= d) x += y; }
    if (lane == 31) wsum[w] = x;
    int excl = x - s;
    __syncthreads();
    if (w == 0) {
        int ws = wsum[lane]; int xx = ws;
#pragma unroll
        for (int d = 1; d < 32; d <<= 1) { int y = __shfl_up_sync(0xffffffffu, xx, d); if (lane >= d) xx += y; }
        wsum[lane] = xx - ws;
    }
    __syncthreads();
    int off = wsum[w] + excl;
#pragma unroll
    for (int i = 0; i < 4; i++) {
        g_off[base + i]  = off + v[i];
        g_size[base + i] = raw[(base + i) * stride];
    }
}

// O[rows x 64] = op(A[rows x 64(PSTR)] @ W[64x64] + bias). 1024 threads.
// Each thread: 2 consecutive rows x 4 cols. Rows >= nrows skipped;
// rows >= nvalid (if >=0) zeroed. TROUT: store transposed.
template<bool RELU, bool TROUT>
__device__ __forceinline__ void gemm_mlp(
    const float* __restrict__ A, const float* __restrict__ W,
    const float* __restrict__ bias, float* __restrict__ O,
    int ostride, int nrows, int nvalid)
{
    const int tx = threadIdx.x & 15, ty = threadIdx.x >> 4;   // ty in [0,64)
    const int r0 = ty << 1;
    if (r0 >= nrows) return;
    const int n0 = tx << 2;
    float acc[2][4];
    const float bx = bias[n0], by = bias[n0 + 1], bz = bias[n0 + 2], bw = bias[n0 + 3];
#pragma unroll
    for (int i = 0; i < 2; i++) { acc[i][0] = bx; acc[i][1] = by; acc[i][2] = bz; acc[i][3] = bw; }
#pragma unroll 8
    for (int k = 0; k < 64; k++) {
        float4 w4 = *(const float4*)(W + k * 64 + n0);
        float a0 = A[(r0 + 0) * PSTR + k];
        float a1 = A[(r0 + 1) * PSTR + k];
        acc[0][0] = fmaf(a0, w4.x, acc[0][0]);
        acc[0][1] = fmaf(a0, w4.y, acc[0][1]);
        acc[0][2] = fmaf(a0, w4.z, acc[0][2]);
        acc[0][3] = fmaf(a0, w4.w, acc[0][3]);
        acc[1][0] = fmaf(a1, w4.x, acc[1][0]);
        acc[1][1] = fmaf(a1, w4.y, acc[1][1]);
        acc[1][2] = fmaf(a1, w4.z, acc[1][2]);
        acc[1][3] = fmaf(a1, w4.w, acc[1][3]);
    }
#pragma unroll
    for (int i = 0; i < 2; i++) {
        int m = r0 + i;
        float o0 = acc[i][0], o1 = acc[i][1], o2 = acc[i][2], o3 = acc[i][3];
        if (RELU) { o0 = fmaxf(o0, 0.f); o1 = fmaxf(o1, 0.f); o2 = fmaxf(o2, 0.f); o3 = fmaxf(o3, 0.f); }
        if (nvalid >= 0 && m >= nvalid) { o0 = 0.f; o1 = 0.f; o2 = 0.f; o3 = 0.f; }
        if (TROUT) {
            O[(n0 + 0) * ostride + m] = o0;
            O[(n0 + 1) * ostride + m] = o1;
            O[(n0 + 2) * ostride + m] = o2;
            O[(n0 + 3) * ostride + m] = o3;
        } else {
            *(float4*)(O + m * ostride + n0) = make_float4(o0, o1, o2, o3);
        }
    }
}

__global__ __launch_bounds__(NTHREADS) void cross_kernel(
    const float* __restrict__ data, const float* __restrict__ W1g,
    const float* __restrict__ b1g, const float* __restrict__ W2g,
    const float* __restrict__ b2g,
    float* __restrict__ res_out, float* __restrict__ s1_out, float* __restrict__ s2_out)
{
    extern __shared__ float smf[];
    float* p1    = smf;
    float* p2    = smf + 8704;
    float* t1    = smf + 17408;
    float* t2T   = smf + 26112;
    float* s2buf = smf + 17408;     // overlays t1+t2T after sim done
    float* hbuf  = smf + 34816;
    float* W1s   = smf + 43520;
    float* W2s   = smf + 47616;
    float* simb  = smf + 34816;     // overlays hbuf+W after MLPs done
    float* rowmax = smf + 51712;
    float* rowinv = smf + 51840;
    float* colmax = smf + 51968;
    float* colinv = smf + 52096;
    float* b1s    = smf + 52224;
    float* b2s    = smf + 52288;

    const int tid = threadIdx.x;
    const int b   = blockIdx.x;
    const int g1 = 2 * b, g2 = 2 * b + 1;
    const int n1 = g_size[g1], n2 = g_size[g2];
    const int off1 = g_off[g1], off2 = g_off[g2];

    // load weights/biases
    for (int i = tid; i < 4096; i += NTHREADS) { W1s[i] = W1g[i]; W2s[i] = W2g[i]; }
    if (tid < 64) { b1s[tid] = b1g[tid]; b2s[tid] = b2g[tid]; }

    // load p1/p2 with zero padding
    for (int it = tid; it < MM * 16; it += NTHREADS) {
        int r = it >> 4, c4 = (it & 15) << 2;
        float4 z = make_float4(0.f, 0.f, 0.f, 0.f);
        float4 v1 = (r < n1) ? *(const float4*)(data + (size_t)(off1 + r) * DIM + c4) : z;
        float4 v2 = (r < n2) ? *(const float4*)(data + (size_t)(off2 + r) * DIM + c4) : z;
        *(float4*)(p1 + r * PSTR + c4) = v1;
        *(float4*)(p2 + r * PSTR + c4) = v2;
    }
    __syncthreads();

    // t1 = mask(relu(p1@W1+b1)@W2+b2) — rows < n1
    gemm_mlp<true, false>(p1, W1s, b1s, hbuf, PSTR, n1, -1);
    __syncthreads();
    gemm_mlp<false, false>(hbuf, W2s, b2s, t1, PSTR, n1, n1);
    __syncthreads();
    // t2T (transposed) — rows < n2
    gemm_mlp<true, false>(p2, W1s, b1s, hbuf, PSTR, n2, -1);
    __syncthreads();
    gemm_mlp<false, true>(hbuf, W2s, b2s, t2T, SSTR, n2, n2);
    __syncthreads();

    // sim[m][n] for warp-rows r0 < n1 (4 rows per warp), all 128 cols.
    {
        const int tx = tid & 31, wrp = tid >> 5;   // wrp in [0,32)
        const int r0 = wrp << 2;
        if (r0 < n1) {
            const int n0 = tx << 2;
            float acc[4][4];
#pragma unroll
            for (int i = 0; i < 4; i++) { acc[i][0] = 0.f; acc[i][1] = 0.f; acc[i][2] = 0.f; acc[i][3] = 0.f; }
#pragma unroll 4
            for (int k = 0; k < 64; k++) {
                float4 w4 = *(const float4*)(t2T + k * SSTR + n0);
#pragma unroll
                for (int i = 0; i < 4; i++) {
                    float a = t1[(r0 + i) * PSTR + k];
                    acc[i][0] = fmaf(a, w4.x, acc[i][0]);
                    acc[i][1] = fmaf(a, w4.y, acc[i][1]);
                    acc[i][2] = fmaf(a, w4.z, acc[i][2]);
                    acc[i][3] = fmaf(a, w4.w, acc[i][3]);
                }
            }
            const bool vb0 = (n0 + 0) < n2, vb1 = (n0 + 1) < n2, vb2 = (n0 + 2) < n2, vb3 = (n0 + 3) < n2;
#pragma unroll
            for (int i = 0; i < 4; i++) {
                int m = r0 + i;
                bool vm = m < n1;
                float o0 = (vm != vb0) ? -CUDART_INF_F : acc[i][0];
                float o1 = (vm != vb1) ? -CUDART_INF_F : acc[i][1];
                float o2 = (vm != vb2) ? -CUDART_INF_F : acc[i][2];
                float o3 = (vm != vb3) ? -CUDART_INF_F : acc[i][3];
                *(float4*)(simb + m * SSTR + n0) = make_float4(o0, o1, o2, o3);
            }
        }
    }
    __syncthreads();

    // stats: 2 threads per row (tid<256), 2 threads per col (tid in [256,512))
    if (tid < 256) {
        int r = tid >> 1, h = tid & 1;
        int c4e = (n2 + 3) >> 2;
        int c4s = h * 16, c4x = min(c4e, c4s + 16);
        float mx = -CUDART_INF_F;
        if (r < n1) {
            const float* row = simb + r * SSTR;
            for (int c4 = c4s; c4 < c4x; c4++) {
                float4 v = *(const float4*)(row + c4 * 4);
                mx = fmaxf(mx, fmaxf(fmaxf(v.x, v.y), fmaxf(v.z, v.w)));
            }
        }
        mx = fmaxf(mx, __shfl_xor_sync(0xffffffffu, mx, 1));
        float s = 0.f;
        if (r < n1) {
            const float* row = simb + r * SSTR;
            for (int c4 = c4s; c4 < c4x; c4++) {
                float4 v = *(const float4*)(row + c4 * 4);
                s += __expf(v.x - mx) + __expf(v.y - mx) + __expf(v.z - mx) + __expf(v.w - mx);
            }
        }
        s += __shfl_xor_sync(0xffffffffu, s, 1);
        if (h == 0 && r < n1) { rowmax[r] = mx; rowinv[r] = 1.f / s; }
    } else if (tid < 512) {
        int c = (tid - 256) >> 1, h = tid & 1;
        int rs = h * 64, re = min(n1, rs + 64);
        float mx = -CUDART_INF_F;
        if (c < n2) {
            for (int r = rs; r < re; r++) mx = fmaxf(mx, simb[r * SSTR + c]);
        }
        mx = fmaxf(mx, __shfl_xor_sync(0xffffffffu, mx, 1));
        float s = 0.f;
        if (c < n2) {
            for (int r = rs; r < re; r++) s += __expf(simb[r * SSTR + c] - mx);
        }
        s += __shfl_xor_sync(0xffffffffu, s, 1);
        if (h == 0) {
            if (c < n2) { colmax[c] = mx; colinv[c] = 1.f / s; }
            else        { colmax[c] = 0.f; colinv[c] = 0.f; }
        }
    }
    __syncthreads();

    // materialize s1/s2 (valid region from sim, invalid analytic), write gmem + smem
    {
        const float inv1 = 1.f / (float)(MM - n1);   // s2 value in both-invalid region
        const float inv2 = 1.f / (float)(MM - n2);   // s1 value in both-invalid region
        for (int it = tid; it < MM * 32; it += NTHREADS) {
            int m = it >> 5, n0 = (it & 31) << 2;
            float4 a, c;
            if (m < n1) {
                float4 v = *(const float4*)(simb + m * SSTR + n0);
                float rm = rowmax[m], ri = rowinv[m];
                float4 cm = *(const float4*)(colmax + n0);
                float4 ci = *(const float4*)(colinv + n0);
                a.x = (n0 + 0 < n2) ? __expf(v.x - rm) * ri : 0.f;
                a.y = (n0 + 1 < n2) ? __expf(v.y - rm) * ri : 0.f;
                a.z = (n0 + 2 < n2) ? __expf(v.z - rm) * ri : 0.f;
                a.w = (n0 + 3 < n2) ? __expf(v.w - rm) * ri : 0.f;
                c.x = (n0 + 0 < n2) ? __expf(v.x - cm.x) * ci.x : 0.f;
                c.y = (n0 + 1 < n2) ? __expf(v.y - cm.y) * ci.y : 0.f;
                c.z = (n0 + 2 < n2) ? __expf(v.z - cm.z) * ci.z : 0.f;
                c.w = (n0 + 3 < n2) ? __expf(v.w - cm.w) * ci.w : 0.f;
            } else {
                a.x = (n0 + 0 < n2) ? 0.f : inv2;
                a.y = (n0 + 1 < n2) ? 0.f : inv2;
                a.z = (n0 + 2 < n2) ? 0.f : inv2;
                a.w = (n0 + 3 < n2) ? 0.f : inv2;
                c.x = (n0 + 0 < n2) ? 0.f : inv1;
                c.y = (n0 + 1 < n2) ? 0.f : inv1;
                c.z = (n0 + 2 < n2) ? 0.f : inv1;
                c.w = (n0 + 3 < n2) ? 0.f : inv1;
            }
            size_t go = (size_t)b * (MM * MM) + (size_t)m * MM + n0;
            *(float4*)(s1_out + go) = a;
            *(float4*)(s2_out + go) = c;
            *(float4*)(simb + m * SSTR + n0) = a;
            *(float4*)(s2buf + m * SSTR + n0) = c;
        }
    }
    __syncthreads();

    // query_new[m<n1] = sum_{n<n2} s1[m][n] p2[n]; corpus_new[nn<n2] = sum_{m<n1} s2[m][nn] p1[m]
    {
        const int tx = tid & 15, ty = tid >> 4;   // ty in [0,64)
        const int d0 = tx << 2;
        const int r0 = ty << 1;
        if (r0 < n1) {
            float acc[2][4];
#pragma unroll
            for (int i = 0; i < 2; i++) { acc[i][0] = 0.f; acc[i][1] = 0.f; acc[i][2] = 0.f; acc[i][3] = 0.f; }
#pragma unroll 4
            for (int n = 0; n < n2; n++) {
                float4 pv = *(const float4*)(p2 + n * PSTR + d0);
                float a0 = simb[(r0 + 0) * SSTR + n];
                float a1 = simb[(r0 + 1) * SSTR + n];
                acc[0][0] = fmaf(a0, pv.x, acc[0][0]);
                acc[0][1] = fmaf(a0, pv.y, acc[0][1]);
                acc[0][2] = fmaf(a0, pv.z, acc[0][2]);
                acc[0][3] = fmaf(a0, pv.w, acc[0][3]);
                acc[1][0] = fmaf(a1, pv.x, acc[1][0]);
                acc[1][1] = fmaf(a1, pv.y, acc[1][1]);
                acc[1][2] = fmaf(a1, pv.z, acc[1][2]);
                acc[1][3] = fmaf(a1, pv.w, acc[1][3]);
            }
#pragma unroll
            for (int i = 0; i < 2; i++) {
                int m = r0 + i;
                if (m < n1)
                    *(float4*)(res_out + (size_t)(off1 + m) * DIM + d0) =
                        make_float4(acc[i][0], acc[i][1], acc[i][2], acc[i][3]);
            }
        }
        if (r0 < n2) {
            float acc2[2][4];
#pragma unroll
            for (int i = 0; i < 2; i++) { acc2[i][0] = 0.f; acc2[i][1] = 0.f; acc2[i][2] = 0.f; acc2[i][3] = 0.f; }
#pragma unroll 4
            for (int m = 0; m < n1; m++) {
                float4 pv = *(const float4*)(p1 + m * PSTR + d0);
                float a0 = s2buf[m * SSTR + r0 + 0];
                float a1 = s2buf[m * SSTR + r0 + 1];
                acc2[0][0] = fmaf(a0, pv.x, acc2[0][0]);
                acc2[0][1] = fmaf(a0, pv.y, acc2[0][1]);
                acc2[0][2] = fmaf(a0, pv.z, acc2[0][2]);
                acc2[0][3] = fmaf(a0, pv.w, acc2[0][3]);
                acc2[1][0] = fmaf(a1, pv.x, acc2[1][0]);
                acc2[1][1] = fmaf(a1, pv.y, acc2[1][1]);
                acc2[1][2] = fmaf(a1, pv.z, acc2[1][2]);
                acc2[1][3] = fmaf(a1, pv.w, acc2[1][3]);
            }
#pragma unroll
            for (int i = 0; i < 2; i++) {
                int nn = r0 + i;
                if (nn < n2)
                    *(float4*)(res_out + (size_t)(off2 + nn) * DIM + d0) =
                        make_float4(acc2[i][0], acc2[i][1], acc2[i][2], acc2[i][3]);
            }
        }
    }
}

extern "C" void kernel_launch(void* const* d_in, const int* in_sizes, int n_in,
                              void* d_out, int out_size) {
    const float* data = (const float*)d_in[0];
    const float* W1   = (const float*)d_in[1];
    const float* b1   = (const float*)d_in[2];
    const float* W2   = (const float*)d_in[3];
    const float* b2   = (const float*)d_in[4];
    const int*   sizes_raw = (const int*)d_in[5];

    float* out = (float*)d_out;
    size_t total_e = (size_t)in_sizes[0];        // total * DIM
    float* s1o = out + total_e;
    float* s2o = s1o + (size_t)NPAIRS * MM * MM;

    cudaFuncSetAttribute(cross_kernel, cudaFuncAttributeMaxDynamicSharedMemorySize, SMEM_BYTES);

    scan_kernel<<<1, 1024>>>(sizes_raw);
    cross_kernel<<<NPAIRS, NTHREADS, SMEM_BYTES>>>(data, W1, b1, W2, b2, out, s1o, s2o);
}

// round 5
// speedup vs baseline: 1.1220x; 1.1220x over previous
#include <cuda_runtime.h>
#include <math_constants.h>

#define NGROUPS 4096
#define NPAIRS  2048
#define DIM     64
#define MM      128
#define PSTR    68    // padded stride for 64-wide tiles (mult of 4 -> float4 aligned)
#define SSTR    132   // padded stride for 128-wide tiles (mult of 4)
#define NTHREADS 512

#define SMEM_BYTES  209408

__device__ int g_off[NGROUPS];
__device__ int g_size[NGROUPS];

// sizes may be int32 or int64 (LE); sizes are in [1,127] so int64 odd words are 0.
__global__ void scan_kernel(const int* __restrict__ raw) {
    __shared__ int wsum[32];
    const int stride =
        (raw[1] == 0 && raw[3] == 0 && raw[5] == 0 && raw[7] == 0) ? 2 : 1;
    int tid = threadIdx.x;              // 1024 threads, 4 items each
    int base = tid * 4;
    int v[4]; int s = 0;
#pragma unroll
    for (int i = 0; i < 4; i++) { v[i] = s; s += raw[(base + i) * stride]; }
    int lane = tid & 31, w = tid >> 5;
    int x = s;
#pragma unroll
    for (int d = 1; d < 32; d <<= 1) { int y = __shfl_up_sync(0xffffffffu, x, d); if (lane >= d) x += y; }
    if (lane == 31) wsum[w] = x;
    int excl = x - s;
    __syncthreads();
    if (w == 0) {
        int ws = wsum[lane]; int xx = ws;
#pragma unroll
        for (int d = 1; d < 32; d <<= 1) { int y = __shfl_up_sync(0xffffffffu, xx, d); if (lane >= d) xx += y; }
        wsum[lane] = xx - ws;
    }
    __syncthreads();
    int off = wsum[w] + excl;
#pragma unroll
    for (int i = 0; i < 4; i++) {
        g_off[base + i]  = off + v[i];
        g_size[base + i] = raw[(base + i) * stride];
    }
}

// O[rows x 64] = op(A[rows x 64(PSTR)] @ W[64x64] + bias). 512 threads.
// Thread tile: 4 rows x 4 cols; k-loop vectorized (float4 on A and W).
template<bool RELU, bool TROUT>
__device__ __forceinline__ void gemm_mlp(
    const float* __restrict__ A, const float* __restrict__ W,
    const float* __restrict__ bias, float* __restrict__ O,
    int ostride, int nrows, int nvalid)
{
    const int tx = threadIdx.x & 15, ty = threadIdx.x >> 4;   // ty in [0,32)
    const int r0 = ty << 2;
    if (r0 >= nrows) return;
    const int n0 = tx << 2;
    float acc[4][4];
    const float bx = bias[n0], by = bias[n0 + 1], bz = bias[n0 + 2], bw = bias[n0 + 3];
#pragma unroll
    for (int i = 0; i < 4; i++) { acc[i][0] = bx; acc[i][1] = by; acc[i][2] = bz; acc[i][3] = bw; }
#pragma unroll 4
    for (int k4 = 0; k4 < 16; k4++) {
        float4 a4[4];
#pragma unroll
        for (int i = 0; i < 4; i++)
            a4[i] = *(const float4*)(A + (r0 + i) * PSTR + (k4 << 2));
#pragma unroll
        for (int kk = 0; kk < 4; kk++) {
            float4 w4 = *(const float4*)(W + ((k4 << 2) + kk) * 64 + n0);
#pragma unroll
            for (int i = 0; i < 4; i++) {
                float a = (kk == 0) ? a4[i].x : (kk == 1) ? a4[i].y : (kk == 2) ? a4[i].z : a4[i].w;
                acc[i][0] = fmaf(a, w4.x, acc[i][0]);
                acc[i][1] = fmaf(a, w4.y, acc[i][1]);
                acc[i][2] = fmaf(a, w4.z, acc[i][2]);
                acc[i][3] = fmaf(a, w4.w, acc[i][3]);
            }
        }
    }
#pragma unroll
    for (int i = 0; i < 4; i++) {
        int m = r0 + i;
        float o0 = acc[i][0], o1 = acc[i][1], o2 = acc[i][2], o3 = acc[i][3];
        if (RELU) { o0 = fmaxf(o0, 0.f); o1 = fmaxf(o1, 0.f); o2 = fmaxf(o2, 0.f); o3 = fmaxf(o3, 0.f); }
        if (nvalid >= 0 && m >= nvalid) { o0 = 0.f; o1 = 0.f; o2 = 0.f; o3 = 0.f; }
        if (TROUT) {
            O[(n0 + 0) * ostride + m] = o0;
            O[(n0 + 1) * ostride + m] = o1;
            O[(n0 + 2) * ostride + m] = o2;
            O[(n0 + 3) * ostride + m] = o3;
        } else {
            *(float4*)(O + m * ostride + n0) = make_float4(o0, o1, o2, o3);
        }
    }
}

__global__ __launch_bounds__(NTHREADS) void cross_kernel(
    const float* __restrict__ data, const float* __restrict__ W1g,
    const float* __restrict__ b1g, const float* __restrict__ W2g,
    const float* __restrict__ b2g,
    float* __restrict__ res_out, float* __restrict__ s1_out, float* __restrict__ s2_out)
{
    extern __shared__ float smf[];
    float* p1    = smf;
    float* p2    = smf + 8704;
    float* t1    = smf + 17408;
    float* t2T   = smf + 26112;
    float* s2buf = smf + 17408;     // overlays t1+t2T after sim done
    float* hbuf  = smf + 34816;
    float* W1s   = smf + 43520;
    float* W2s   = smf + 47616;
    float* simb  = smf + 34816;     // overlays hbuf+W after MLPs done
    float* rowmax = smf + 51712;
    float* rowinv = smf + 51840;
    float* colmax = smf + 51968;
    float* colinv = smf + 52096;
    float* b1s    = smf + 52224;
    float* b2s    = smf + 52288;

    const int tid = threadIdx.x;
    const int b   = blockIdx.x;
    const int g1 = 2 * b, g2 = 2 * b + 1;
    const int n1 = g_size[g1], n2 = g_size[g2];
    const int off1 = g_off[g1], off2 = g_off[g2];

    // load weights/biases
    for (int i = tid; i < 4096; i += NTHREADS) { W1s[i] = W1g[i]; W2s[i] = W2g[i]; }
    if (tid < 64) { b1s[tid] = b1g[tid]; b2s[tid] = b2g[tid]; }

    // load p1/p2 with zero padding
    for (int it = tid; it < MM * 16; it += NTHREADS) {
        int r = it >> 4, c4 = (it & 15) << 2;
        float4 z = make_float4(0.f, 0.f, 0.f, 0.f);
        float4 v1 = (r < n1) ? *(const float4*)(data + (size_t)(off1 + r) * DIM + c4) : z;
        float4 v2 = (r < n2) ? *(const float4*)(data + (size_t)(off2 + r) * DIM + c4) : z;
        *(float4*)(p1 + r * PSTR + c4) = v1;
        *(float4*)(p2 + r * PSTR + c4) = v2;
    }
    __syncthreads();

    // t1 = mask(relu(p1@W1+b1)@W2+b2) — rows < n1
    gemm_mlp<true, false>(p1, W1s, b1s, hbuf, PSTR, n1, -1);
    __syncthreads();
    gemm_mlp<false, false>(hbuf, W2s, b2s, t1, PSTR, n1, n1);
    __syncthreads();
    // t2T (transposed) — rows < n2
    gemm_mlp<true, false>(p2, W1s, b1s, hbuf, PSTR, n2, -1);
    __syncthreads();
    gemm_mlp<false, true>(hbuf, W2s, b2s, t2T, SSTR, n2, n2);
    __syncthreads();

    // sim[m][n]: 16 warps x 8 rows each, warp skips if r0 >= n1. All 128 cols.
    {
        const int tx = tid & 31, wrp = tid >> 5;   // wrp in [0,16)
        const int r0 = wrp << 3;
        if (r0 < n1) {
            const int n0 = tx << 2;
            float acc[8][4];
#pragma unroll
            for (int i = 0; i < 8; i++) { acc[i][0] = 0.f; acc[i][1] = 0.f; acc[i][2] = 0.f; acc[i][3] = 0.f; }
#pragma unroll 2
            for (int k4 = 0; k4 < 16; k4++) {
                float4 a4[8];
#pragma unroll
                for (int i = 0; i < 8; i++)
                    a4[i] = *(const float4*)(t1 + (r0 + i) * PSTR + (k4 << 2));
#pragma unroll
                for (int kk = 0; kk < 4; kk++) {
                    float4 w4 = *(const float4*)(t2T + ((k4 << 2) + kk) * SSTR + n0);
#pragma unroll
                    for (int i = 0; i < 8; i++) {
                        float a = (kk == 0) ? a4[i].x : (kk == 1) ? a4[i].y : (kk == 2) ? a4[i].z : a4[i].w;
                        acc[i][0] = fmaf(a, w4.x, acc[i][0]);
                        acc[i][1] = fmaf(a, w4.y, acc[i][1]);
                        acc[i][2] = fmaf(a, w4.z, acc[i][2]);
                        acc[i][3] = fmaf(a, w4.w, acc[i][3]);
                    }
                }
            }
            const bool vb0 = (n0 + 0) < n2, vb1 = (n0 + 1) < n2, vb2 = (n0 + 2) < n2, vb3 = (n0 + 3) < n2;
#pragma unroll
            for (int i = 0; i < 8; i++) {
                int m = r0 + i;
                bool vm = m < n1;
                float o0 = (vm != vb0) ? -CUDART_INF_F : acc[i][0];
                float o1 = (vm != vb1) ? -CUDART_INF_F : acc[i][1];
                float o2 = (vm != vb2) ? -CUDART_INF_F : acc[i][2];
                float o3 = (vm != vb3) ? -CUDART_INF_F : acc[i][3];
                *(float4*)(simb + m * SSTR + n0) = make_float4(o0, o1, o2, o3);
            }
        }
    }
    __syncthreads();

    // stats: 2 threads per row (tid<256), 2 threads per col (tid in [256,512))
    if (tid < 256) {
        int r = tid >> 1, h = tid & 1;
        int c4e = (n2 + 3) >> 2;
        int c4s = h * 16, c4x = min(c4e, c4s + 16);
        float mx = -CUDART_INF_F;
        if (r < n1) {
            const float* row = simb + r * SSTR;
            for (int c4 = c4s; c4 < c4x; c4++) {
                float4 v = *(const float4*)(row + c4 * 4);
                mx = fmaxf(mx, fmaxf(fmaxf(v.x, v.y), fmaxf(v.z, v.w)));
            }
        }
        mx = fmaxf(mx, __shfl_xor_sync(0xffffffffu, mx, 1));
        float s = 0.f;
        if (r < n1) {
            const float* row = simb + r * SSTR;
            for (int c4 = c4s; c4 < c4x; c4++) {
                float4 v = *(const float4*)(row + c4 * 4);
                s += __expf(v.x - mx) + __expf(v.y - mx) + __expf(v.z - mx) + __expf(v.w - mx);
            }
        }
        s += __shfl_xor_sync(0xffffffffu, s, 1);
        if (h == 0 && r < n1) { rowmax[r] = mx; rowinv[r] = 1.f / s; }
    } else {
        int c = (tid - 256) >> 1, h = tid & 1;
        int rs = h * 64, re = min(n1, rs + 64);
        float mx = -CUDART_INF_F;
        if (c < n2) {
            for (int r = rs; r < re; r++) mx = fmaxf(mx, simb[r * SSTR + c]);
        }
        mx = fmaxf(mx, __shfl_xor_sync(0xffffffffu, mx, 1));
        float s = 0.f;
        if (c < n2) {
            for (int r = rs; r < re; r++) s += __expf(simb[r * SSTR + c] - mx);
        }
        s += __shfl_xor_sync(0xffffffffu, s, 1);
        if (h == 0) {
            if (c < n2) { colmax[c] = mx; colinv[c] = 1.f / s; }
            else        { colmax[c] = 0.f; colinv[c] = 0.f; }
        }
    }
    __syncthreads();

    // materialize s1/s2 (valid region from sim, invalid analytic), write gmem + smem
    {
        const float inv1 = 1.f / (float)(MM - n1);   // s2 value in both-invalid region
        const float inv2 = 1.f / (float)(MM - n2);   // s1 value in both-invalid region
        for (int it = tid; it < MM * 32; it += NTHREADS) {
            int m = it >> 5, n0 = (it & 31) << 2;
            float4 a, c;
            if (m < n1) {
                float4 v = *(const float4*)(simb + m * SSTR + n0);
                float rm = rowmax[m], ri = rowinv[m];
                float4 cm = *(const float4*)(colmax + n0);
                float4 ci = *(const float4*)(colinv + n0);
                a.x = (n0 + 0 < n2) ? __expf(v.x - rm) * ri : 0.f;
                a.y = (n0 + 1 < n2) ? __expf(v.y - rm) * ri : 0.f;
                a.z = (n0 + 2 < n2) ? __expf(v.z - rm) * ri : 0.f;
                a.w = (n0 + 3 < n2) ? __expf(v.w - rm) * ri : 0.f;
                c.x = (n0 + 0 < n2) ? __expf(v.x - cm.x) * ci.x : 0.f;
                c.y = (n0 + 1 < n2) ? __expf(v.y - cm.y) * ci.y : 0.f;
                c.z = (n0 + 2 < n2) ? __expf(v.z - cm.z) * ci.z : 0.f;
                c.w = (n0 + 3 < n2) ? __expf(v.w - cm.w) * ci.w : 0.f;
            } else {
                a.x = (n0 + 0 < n2) ? 0.f : inv2;
                a.y = (n0 + 1 < n2) ? 0.f : inv2;
                a.z = (n0 + 2 < n2) ? 0.f : inv2;
                a.w = (n0 + 3 < n2) ? 0.f : inv2;
                c.x = (n0 + 0 < n2) ? 0.f : inv1;
                c.y = (n0 + 1 < n2) ? 0.f : inv1;
                c.z = (n0 + 2 < n2) ? 0.f : inv1;
                c.w = (n0 + 3 < n2) ? 0.f : inv1;
            }
            size_t go = (size_t)b * (MM * MM) + (size_t)m * MM + n0;
            *(float4*)(s1_out + go) = a;
            *(float4*)(s2_out + go) = c;
            *(float4*)(simb + m * SSTR + n0) = a;
            *(float4*)(s2buf + m * SSTR + n0) = c;
        }
    }
    __syncthreads();

    // query_new[m<n1] = sum_{n<n2} s1[m][n] p2[n]; corpus_new[nn<n2] = sum_{m<n1} s2[m][nn] p1[m]
    // Padded s1/s2 entries in these ranges are exactly 0, so full float4 blocks are safe.
    {
        const int tx = tid & 15, ty = tid >> 4;   // ty in [0,32)
        const int d0 = tx << 2;
        const int r0 = ty << 2;
        if (r0 < n1) {
            float acc[4][4];
#pragma unroll
            for (int i = 0; i < 4; i++) { acc[i][0] = 0.f; acc[i][1] = 0.f; acc[i][2] = 0.f; acc[i][3] = 0.f; }
            const int nblk = (n2 + 3) >> 2;
#pragma unroll 2
            for (int n4 = 0; n4 < nblk; n4++) {
                float4 a4[4];
#pragma unroll
                for (int i = 0; i < 4; i++)
                    a4[i] = *(const float4*)(simb + (r0 + i) * SSTR + (n4 << 2));
#pragma unroll
                for (int j = 0; j < 4; j++) {
                    float4 pv = *(const float4*)(p2 + ((n4 << 2) + j) * PSTR + d0);
#pragma unroll
                    for (int i = 0; i < 4; i++) {
                        float a = (j == 0) ? a4[i].x : (j == 1) ? a4[i].y : (j == 2) ? a4[i].z : a4[i].w;
                        acc[i][0] = fmaf(a, pv.x, acc[i][0]);
                        acc[i][1] = fmaf(a, pv.y, acc[i][1]);
                        acc[i][2] = fmaf(a, pv.z, acc[i][2]);
                        acc[i][3] = fmaf(a, pv.w, acc[i][3]);
                    }
                }
            }
#pragma unroll
            for (int i = 0; i < 4; i++) {
                int m = r0 + i;
                if (m < n1)
                    *(float4*)(res_out + (size_t)(off1 + m) * DIM + d0) =
                        make_float4(acc[i][0], acc[i][1], acc[i][2], acc[i][3]);
            }
        }
        if (r0 < n2) {
            float acc2[4][4];
#pragma unroll
            for (int i = 0; i < 4; i++) { acc2[i][0] = 0.f; acc2[i][1] = 0.f; acc2[i][2] = 0.f; acc2[i][3] = 0.f; }
            const int mblk = (n1 + 3) >> 2;
#pragma unroll 2
            for (int m4 = 0; m4 < mblk; m4++) {
                float4 s4[4];   // s4[j] = s2[m4*4+j][r0..r0+3]
#pragma unroll
                for (int j = 0; j < 4; j++)
                    s4[j] = *(const float4*)(s2buf + ((m4 << 2) + j) * SSTR + r0);
#pragma unroll
                for (int j = 0; j < 4; j++) {
                    float4 pv = *(const float4*)(p1 + ((m4 << 2) + j) * PSTR + d0);
                    acc2[0][0] = fmaf(s4[j].x, pv.x, acc2[0][0]);
                    acc2[0][1] = fmaf(s4[j].x, pv.y, acc2[0][1]);
                    acc2[0][2] = fmaf(s4[j].x, pv.z, acc2[0][2]);
                    acc2[0][3] = fmaf(s4[j].x, pv.w, acc2[0][3]);
                    acc2[1][0] = fmaf(s4[j].y, pv.x, acc2[1][0]);
                    acc2[1][1] = fmaf(s4[j].y, pv.y, acc2[1][1]);
                    acc2[1][2] = fmaf(s4[j].y, pv.z, acc2[1][2]);
                    acc2[1][3] = fmaf(s4[j].y, pv.w, acc2[1][3]);
                    acc2[2][0] = fmaf(s4[j].z, pv.x, acc2[2][0]);
                    acc2[2][1] = fmaf(s4[j].z, pv.y, acc2[2][1]);
                    acc2[2][2] = fmaf(s4[j].z, pv.z, acc2[2][2]);
                    acc2[2][3] = fmaf(s4[j].z, pv.w, acc2[2][3]);
                    acc2[3][0] = fmaf(s4[j].w, pv.x, acc2[3][0]);
                    acc2[3][1] = fmaf(s4[j].w, pv.y, acc2[3][1]);
                    acc2[3][2] = fmaf(s4[j].w, pv.z, acc2[3][2]);
                    acc2[3][3] = fmaf(s4[j].w, pv.w, acc2[3][3]);
                }
            }
#pragma unroll
            for (int i = 0; i < 4; i++) {
                int nn = r0 + i;
                if (nn < n2)
                    *(float4*)(res_out + (size_t)(off2 + nn) * DIM + d0) =
                        make_float4(acc2[i][0], acc2[i][1], acc2[i][2], acc2[i][3]);
            }
        }
    }
}

extern "C" void kernel_launch(void* const* d_in, const int* in_sizes, int n_in,
                              void* d_out, int out_size) {
    const float* data = (const float*)d_in[0];
    const float* W1   = (const float*)d_in[1];
    const float* b1   = (const float*)d_in[2];
    const float* W2   = (const float*)d_in[3];
    const float* b2   = (const float*)d_in[4];
    const int*   sizes_raw = (const int*)d_in[5];

    float* out = (float*)d_out;
    size_t total_e = (size_t)in_sizes[0];        // total * DIM
    float* s1o = out + total_e;
    float* s2o = s1o + (size_t)NPAIRS * MM * MM;

    cudaFuncSetAttribute(cross_kernel, cudaFuncAttributeMaxDynamicSharedMemorySize, SMEM_BYTES);

    scan_kernel<<<1, 1024>>>(sizes_raw);
    cross_kernel<<<NPAIRS, NTHREADS, SMEM_BYTES>>>(data, W1, b1, W2, b2, out, s1o, s2o);
}